// round 12
// baseline (speedup 1.0000x reference)
#include <cuda_runtime.h>
#include <cuda_fp16.h>
#include <math.h>
#include <stdint.h>

// Problem constants
#define HID   2048
#define MTOT  4096          // B*S = 2*2048
#define KVD   256           // N_KV * HEAD_DIM
#define HD    128
#define SCALING 0.08838834764831845f  // 128^-0.5

// GEMM smem geometry, 128x128 path (oproj)
#define LDT    40                       // padded row length (halves); 80B rows
#define TILEB  (128 * LDT * 2)          // one 128x32 fp16 tile = 10240 B
#define STAGE  (2 * TILEB)              // A + B = 20480 B
#define GSMEM  (4 * STAGE)              // 4-stage = 81920 B

// GEMM smem geometry, 64x128 path (qkv, 3 CTAs/SM)
#define ATILE64 (64 * LDT * 2)          // 5120 B
#define BTILE64 (128 * LDT * 2)         // 10240 B
#define STAGE64 (ATILE64 + BTILE64)     // 15360 B
#define GSMEM64 (4 * STAGE64)           // 61440 B

// ---------------------------------------------------------------------------
// Scratch (device globals; no runtime allocation allowed)
// ---------------------------------------------------------------------------
__device__ __half g_Qh[(size_t)MTOT * HID];
__device__ __half g_Kh[(size_t)MTOT * KVD];
__device__ __half g_Vh[(size_t)MTOT * KVD];
__device__ __half g_ATh[(size_t)MTOT * HID];

__device__ __half g_Xh[(size_t)MTOT * HID];
__device__ __half g_WqTh[(size_t)HID * HID];
__device__ __half g_WkTh[(size_t)KVD * HID];
__device__ __half g_WvTh[(size_t)KVD * HID];
__device__ __half g_WoTh[(size_t)HID * HID];

// ---------------------------------------------------------------------------
// Helpers
// ---------------------------------------------------------------------------
__device__ __forceinline__ uint32_t smem_u32(const void* p) {
    uint32_t a;
    asm("{ .reg .u64 t; cvta.to.shared.u64 t, %1; cvt.u32.u64 %0, t; }"
        : "=r"(a) : "l"(p));
    return a;
}
__device__ __forceinline__ void cp16(uint32_t sa, const void* ga) {
    asm volatile("cp.async.cg.shared.global [%0], [%1], 16;"
                 :: "r"(sa), "l"(ga) : "memory");
}
#define CP_COMMIT() asm volatile("cp.async.commit_group;" ::: "memory")

__device__ __forceinline__ void ldsm_x4(uint32_t& r0, uint32_t& r1,
                                        uint32_t& r2, uint32_t& r3, uint32_t a) {
    asm volatile("ldmatrix.sync.aligned.m8n8.x4.shared.b16 {%0,%1,%2,%3}, [%4];"
                 : "=r"(r0), "=r"(r1), "=r"(r2), "=r"(r3) : "r"(a));
}
__device__ __forceinline__ void ldsm_x4_t(uint32_t& r0, uint32_t& r1,
                                          uint32_t& r2, uint32_t& r3, uint32_t a) {
    asm volatile("ldmatrix.sync.aligned.m8n8.x4.trans.shared.b16 {%0,%1,%2,%3}, [%4];"
                 : "=r"(r0), "=r"(r1), "=r"(r2), "=r"(r3) : "r"(a));
}
__device__ __forceinline__ void mma_fp16(float* c, const uint32_t* a,
                                         const uint32_t* b) {
    asm volatile(
        "mma.sync.aligned.m16n8k16.row.col.f32.f16.f16.f32 "
        "{%0,%1,%2,%3}, {%4,%5,%6,%7}, {%8,%9}, {%0,%1,%2,%3};"
        : "+f"(c[0]), "+f"(c[1]), "+f"(c[2]), "+f"(c[3])
        : "r"(a[0]), "r"(a[1]), "r"(a[2]), "r"(a[3]), "r"(b[0]), "r"(b[1]));
}

// ---------------------------------------------------------------------------
// Merged converts: fp32 -> fp16 (X rows + 4 transposed weights), one kernel.
// ---------------------------------------------------------------------------
__device__ __forceinline__ void conv_T_tile(
    const float* __restrict__ W, __half* __restrict__ WT,
    int N, int K, int bx, int by, float* tile /* [32][33] */)
{
    int n0 = bx * 32, k0 = by * 32;
    int tx = threadIdx.x & 31, ty = threadIdx.x >> 5;
#pragma unroll
    for (int j = 0; j < 4; ++j)
        tile[(ty + 8 * j) * 33 + tx] = W[(size_t)(k0 + ty + 8 * j) * N + n0 + tx];
    __syncthreads();
#pragma unroll
    for (int j = 0; j < 4; ++j) {
        int nn = n0 + ty + 8 * j;
        WT[(size_t)nn * K + k0 + tx] = __float2half_rn(tile[tx * 33 + ty + 8 * j]);
    }
}

__global__ __launch_bounds__(256)
void convert_all(const float* __restrict__ X,
                 const float* __restrict__ Wq, const float* __restrict__ Wk,
                 const float* __restrict__ Wv, const float* __restrict__ Wo,
                 __half* __restrict__ xh, __half* __restrict__ wqh,
                 __half* __restrict__ wkh, __half* __restrict__ wvh,
                 __half* __restrict__ woh)
{
    __shared__ float tile[32 * 33];
    int id = blockIdx.x;
    if (id < 8192) {
        size_t i = ((size_t)id * 256 + threadIdx.x) * 4;
        float4 v = *(const float4*)(X + i);
        *(__half2*)(xh + i)     = __floats2half2_rn(v.x, v.y);
        *(__half2*)(xh + i + 2) = __floats2half2_rn(v.z, v.w);
        return;
    }
    id -= 8192;
    if (id < 4096)      { conv_T_tile(Wq, wqh, HID, HID, id & 63, id >> 6, tile); return; }
    id -= 4096;
    if (id < 512)       { conv_T_tile(Wk, wkh, KVD, HID, id & 7,  id >> 3, tile); return; }
    id -= 512;
    if (id < 512)       { conv_T_tile(Wv, wvh, KVD, HID, id & 7,  id >> 3, tile); return; }
    id -= 512;
    conv_T_tile(Wo, woh, HID, HID, id & 63, id >> 6, tile);
}

// ---------------------------------------------------------------------------
// QKV GEMM (unchanged from R11): 64x128 tiles, 128 threads, 4 warps, 3 CTAs/SM.
// ---------------------------------------------------------------------------
__device__ void gemm64_body(
    const __half* __restrict__ A, const __half* __restrict__ B,
    const float* __restrict__ bias, __half* __restrict__ Ch,
    int ldc, int m0, int n0, float scale, char* smb)
{
    const int t    = threadIdx.x;
    const int lane = t & 31, wid = t >> 5;
    const int wm   = wid & 1, wn = wid >> 1;
    const int g    = lane >> 2, tg = lane & 3;
    const int l15  = lane & 15, l7 = lane & 7;
    const int hi16 = lane >> 4, k8 = (lane >> 3) & 1;
    const uint32_t sb = smem_u32(smb);

    float acc[2][8][4];
#pragma unroll
    for (int im = 0; im < 2; ++im)
#pragma unroll
        for (int in = 0; in < 8; ++in)
#pragma unroll
            for (int r = 0; r < 4; ++r) acc[im][in][r] = 0.f;

    auto prefetch = [&](int s) {
        const uint32_t base = sb + (uint32_t)(s & 3) * STAGE64;
        const int k0 = s * 32;
#pragma unroll
        for (int i = 0; i < 2; ++i) {
            int idx = t + 128 * i;
            int r = idx >> 2, c = idx & 3;
            cp16(base + (uint32_t)(r * LDT + c * 8) * 2,
                 A + (size_t)(m0 + r) * HID + k0 + c * 8);
        }
#pragma unroll
        for (int i = 0; i < 4; ++i) {
            int idx = t + 128 * i;
            int r = idx >> 2, c = idx & 3;
            cp16(base + ATILE64 + (uint32_t)(r * LDT + c * 8) * 2,
                 B + (size_t)(n0 + r) * HID + k0 + c * 8);
        }
        CP_COMMIT();
    };

    prefetch(0); prefetch(1); prefetch(2);

    for (int s = 0; s < 64; ++s) {
        if (s < 62)       asm volatile("cp.async.wait_group 2;" ::: "memory");
        else if (s == 62) asm volatile("cp.async.wait_group 1;" ::: "memory");
        else              asm volatile("cp.async.wait_group 0;" ::: "memory");
        __syncthreads();
        if (s + 3 < 64) prefetch(s + 3);

        const uint32_t base = sb + (uint32_t)(s & 3) * STAGE64;
#pragma unroll
        for (int kk = 0; kk < 32; kk += 16) {
            uint32_t ah[2][4], bh[8][2];
#pragma unroll
            for (int im = 0; im < 2; ++im) {
                uint32_t ao = base +
                    (uint32_t)((wm * 32 + im * 16 + l15) * LDT + kk) * 2 + hi16 * 16;
                ldsm_x4(ah[im][0], ah[im][1], ah[im][2], ah[im][3], ao);
            }
#pragma unroll
            for (int p = 0; p < 4; ++p) {
                uint32_t bo = base + ATILE64 +
                    (uint32_t)((wn * 64 + p * 16 + l7 + hi16 * 8) * LDT + kk) * 2 + k8 * 16;
                uint32_t r0, r1, r2, r3;
                ldsm_x4(r0, r1, r2, r3, bo);
                bh[2 * p][0] = r0;     bh[2 * p][1] = r1;
                bh[2 * p + 1][0] = r2; bh[2 * p + 1][1] = r3;
            }
#pragma unroll
            for (int im = 0; im < 2; ++im)
#pragma unroll
                for (int in = 0; in < 8; ++in)
                    mma_fp16(acc[im][in], ah[im], bh[in]);
        }
    }

#pragma unroll
    for (int im = 0; im < 2; ++im) {
#pragma unroll
        for (int in = 0; in < 8; ++in) {
            int row = m0 + wm * 32 + im * 16 + g;
            int col = n0 + wn * 64 + in * 8 + 2 * tg;
            float2 b2 = *(const float2*)(bias + col);
            *(__half2*)(Ch + (size_t)row * ldc + col) =
                __floats2half2_rn((acc[im][in][0] + b2.x) * scale,
                                  (acc[im][in][1] + b2.y) * scale);
            *(__half2*)(Ch + (size_t)(row + 8) * ldc + col) =
                __floats2half2_rn((acc[im][in][2] + b2.x) * scale,
                                  (acc[im][in][3] + b2.y) * scale);
        }
    }
}

__global__ __launch_bounds__(128, 3)
void qkv_mma(const float* __restrict__ bq, const float* __restrict__ bk,
             const float* __restrict__ bv)
{
    extern __shared__ char smb[];
    int gx = blockIdx.x >> 6, my = blockIdx.x & 63;
    int m0 = my * 64;
    if (gx < 16) {
        gemm64_body(g_Xh, g_WqTh, bq, g_Qh, HID, m0, gx * 128, SCALING, smb);
    } else if (gx < 18) {
        gemm64_body(g_Xh, g_WkTh, bk, g_Kh, KVD, m0, (gx - 16) * 128, 1.f, smb);
    } else {
        gemm64_body(g_Xh, g_WvTh, bv, g_Vh, KVD, m0, (gx - 18) * 128, 1.f, smb);
    }
}

// ---------------------------------------------------------------------------
// O-proj GEMM v3: 256 threads, 8 warps (4m x 2n), warp tile 32x64,
// CTA tile 128x128, 4-stage cp.async. 16 warps/SM at 2 CTAs/SM.
// ---------------------------------------------------------------------------
__global__ __launch_bounds__(256, 2)
void oproj_mma(const float* __restrict__ bo, float* __restrict__ out)
{
    extern __shared__ char smb[];
    const int t    = threadIdx.x;                 // 0..255
    const int lane = t & 31, wid = t >> 5;        // 8 warps
    const int wm   = wid & 3;        // 0..3 (32-row quarter)
    const int wn   = wid >> 2;       // 0..1 (64-col half)
    const int g    = lane >> 2, tg = lane & 3;
    const int l15  = lane & 15, l7 = lane & 7;
    const int hi16 = lane >> 4, k8 = (lane >> 3) & 1;
    const int m0 = blockIdx.y * 128, n0 = blockIdx.x * 128;
    const uint32_t sb = smem_u32(smb);
    const __half* A = g_ATh;
    const __half* B = g_WoTh;

    float acc[2][8][4];
#pragma unroll
    for (int im = 0; im < 2; ++im)
#pragma unroll
        for (int in = 0; in < 8; ++in)
#pragma unroll
            for (int r = 0; r < 4; ++r) acc[im][in][r] = 0.f;

    auto prefetch = [&](int s) {
        const uint32_t base = sb + (uint32_t)(s & 3) * STAGE;
        const int k0 = s * 32;
#pragma unroll
        for (int i = 0; i < 2; ++i) {
            int idx = t + 256 * i;          // 0..511
            int r = idx >> 2, c = idx & 3;
            uint32_t so = base + (uint32_t)(r * LDT + c * 8) * 2;
            cp16(so,         A + (size_t)(m0 + r) * HID + k0 + c * 8);
            cp16(so + TILEB, B + (size_t)(n0 + r) * HID + k0 + c * 8);
        }
        CP_COMMIT();
    };

    prefetch(0); prefetch(1); prefetch(2);

    for (int s = 0; s < 64; ++s) {
        if (s < 62)       asm volatile("cp.async.wait_group 2;" ::: "memory");
        else if (s == 62) asm volatile("cp.async.wait_group 1;" ::: "memory");
        else              asm volatile("cp.async.wait_group 0;" ::: "memory");
        __syncthreads();
        if (s + 3 < 64) prefetch(s + 3);

        const uint32_t base = sb + (uint32_t)(s & 3) * STAGE;
#pragma unroll
        for (int kk = 0; kk < 32; kk += 16) {
            uint32_t ah[2][4], bh[8][2];
#pragma unroll
            for (int im = 0; im < 2; ++im) {
                uint32_t ao = base +
                    (uint32_t)((wm * 32 + im * 16 + l15) * LDT + kk) * 2 + hi16 * 16;
                ldsm_x4(ah[im][0], ah[im][1], ah[im][2], ah[im][3], ao);
            }
#pragma unroll
            for (int p = 0; p < 4; ++p) {
                uint32_t bo2 = base + TILEB +
                    (uint32_t)((wn * 64 + p * 16 + l7 + hi16 * 8) * LDT + kk) * 2 + k8 * 16;
                uint32_t r0, r1, r2, r3;
                ldsm_x4(r0, r1, r2, r3, bo2);
                bh[2 * p][0] = r0;     bh[2 * p][1] = r1;
                bh[2 * p + 1][0] = r2; bh[2 * p + 1][1] = r3;
            }
#pragma unroll
            for (int im = 0; im < 2; ++im)
#pragma unroll
                for (int in = 0; in < 8; ++in)
                    mma_fp16(acc[im][in], ah[im], bh[in]);
        }
    }

#pragma unroll
    for (int im = 0; im < 2; ++im) {
#pragma unroll
        for (int in = 0; in < 8; ++in) {
            int row = m0 + wm * 32 + im * 16 + g;
            int col = n0 + wn * 64 + in * 8 + 2 * tg;
            float2 b2 = *(const float2*)(bo + col);
            *(float2*)(out + (size_t)row * HID + col) =
                make_float2(acc[im][in][0] + b2.x, acc[im][in][1] + b2.y);
            *(float2*)(out + (size_t)(row + 8) * HID + col) =
                make_float2(acc[im][in][2] + b2.x, acc[im][in][3] + b2.y);
        }
    }
}

// ---------------------------------------------------------------------------
// Flash attention v2: 256 threads, 8 warps, Br=128 per CTA (16 rows/warp),
// Bc=64, D=128. Q frags re-loaded per iteration (register relief).
// grid = (16 qblocks, 32 bh). smem: Q[128][136] + K0,K1,V0,V1 [64][136].
// ---------------------------------------------------------------------------
#define FL_LDK  136
#define FL_TILE (64 * FL_LDK * 2)        // 17408 B
#define FL_QTILE (128 * FL_LDK * 2)      // 34816 B
#define FL_SMEM (FL_QTILE + 4 * FL_TILE) // 104448 B

__global__ __launch_bounds__(256, 2)
void flash_mma()
{
    extern __shared__ __half fsm[];
    const uint32_t sQ  = smem_u32(fsm);
    const uint32_t sK0 = sQ + FL_QTILE;
    const uint32_t sV0 = sQ + FL_QTILE + 2 * FL_TILE;

    const int t = threadIdx.x, lane = t & 31, warp = t >> 5;   // 8 warps
    const int g = lane >> 2, tg = lane & 3;
    const int l15 = lane & 15, l7 = lane & 7;
    const int hi16 = lane >> 4, k8 = (lane >> 3) & 1;
    const int bh = blockIdx.y, b = bh >> 4, h = bh & 15, kvh = h >> 3;
    const int q0 = blockIdx.x * 128;
    const size_t qrow0 = (size_t)(b * 2048 + q0);
    const int wr = warp * 16;                                   // 0..112

    auto prefetch_kv = [&](int kb) {
        const uint32_t buf = (uint32_t)(kb & 1) * FL_TILE;
        const size_t krow0 = (size_t)(b * 2048 + kb * 64);
#pragma unroll
        for (int s = 0; s < 4; ++s) {
            int i = t + 256 * s;             // 0..1023
            int r = i >> 4, c = i & 15;      // r 0..63, 16 chunks/row
            uint32_t so = (uint32_t)(r * FL_LDK + c * 8) * 2;
            size_t go = (krow0 + r) * KVD + kvh * HD + c * 8;
            cp16(sK0 + buf + so, g_Kh + go);
            cp16(sV0 + buf + so, g_Vh + go);
        }
        CP_COMMIT();
    };

    prefetch_kv(0);

    // Stage Q tile 128x128 fp16: 2048 chunks, 256 threads x 8 iters
#pragma unroll
    for (int s = 0; s < 8; ++s) {
        int i = t + 256 * s;
        int r = i >> 4, c = i & 15;
        *(uint4*)(fsm + r * FL_LDK + c * 8) =
            *(const uint4*)(g_Qh + (qrow0 + r) * HID + h * HD + c * 8);
    }
    __syncthreads();

    float oacc[16][4];
#pragma unroll
    for (int j = 0; j < 16; ++j)
#pragma unroll
        for (int r = 0; r < 4; ++r) oacc[j][r] = 0.f;
    float mrow0 = -1e30f, mrow1 = -1e30f, lrow0 = 0.f, lrow1 = 0.f;

    for (int kb = 0; kb < 32; ++kb) {
        asm volatile("cp.async.wait_group 0;" ::: "memory");
        __syncthreads();
        if (kb + 1 < 32) prefetch_kv(kb + 1);

        const uint32_t sK = sK0 + (uint32_t)(kb & 1) * FL_TILE;
        const uint32_t sV = sV0 + (uint32_t)(kb & 1) * FL_TILE;

        // S = Q @ K^T : 8 n8-tiles; Q frags loaded per k-step
        float sacc[8][4];
#pragma unroll
        for (int j = 0; j < 8; ++j)
#pragma unroll
            for (int r = 0; r < 4; ++r) sacc[j][r] = 0.f;
#pragma unroll
        for (int ks = 0; ks < 8; ++ks) {
            uint32_t aQ[4];
            uint32_t ao = sQ + (uint32_t)((wr + l15) * FL_LDK + ks * 16) * 2 + hi16 * 16;
            ldsm_x4(aQ[0], aQ[1], aQ[2], aQ[3], ao);
#pragma unroll
            for (int p = 0; p < 4; ++p) {
                uint32_t bo = sK +
                    (uint32_t)((p * 16 + l7 + hi16 * 8) * FL_LDK + ks * 16) * 2 + k8 * 16;
                uint32_t r0, r1, r2, r3;
                ldsm_x4(r0, r1, r2, r3, bo);
                uint32_t b0[2] = {r0, r1}, b1[2] = {r2, r3};
                mma_fp16(sacc[2 * p], aQ, b0);
                mma_fp16(sacc[2 * p + 1], aQ, b1);
            }
        }

        // Online softmax (rows g and g+8 of warp tile)
        float mx0 = -1e30f, mx1 = -1e30f;
#pragma unroll
        for (int j = 0; j < 8; ++j) {
            mx0 = fmaxf(mx0, fmaxf(sacc[j][0], sacc[j][1]));
            mx1 = fmaxf(mx1, fmaxf(sacc[j][2], sacc[j][3]));
        }
        mx0 = fmaxf(mx0, __shfl_xor_sync(0xffffffffu, mx0, 1));
        mx0 = fmaxf(mx0, __shfl_xor_sync(0xffffffffu, mx0, 2));
        mx1 = fmaxf(mx1, __shfl_xor_sync(0xffffffffu, mx1, 1));
        mx1 = fmaxf(mx1, __shfl_xor_sync(0xffffffffu, mx1, 2));
        float mn0 = fmaxf(mrow0, mx0), mn1 = fmaxf(mrow1, mx1);
        float al0 = __expf(mrow0 - mn0), al1 = __expf(mrow1 - mn1);
        mrow0 = mn0; mrow1 = mn1;

        uint32_t aP[4][4];
        float s0 = 0.f, s1 = 0.f;
#pragma unroll
        for (int j = 0; j < 8; ++j) {
            float p0 = __expf(sacc[j][0] - mn0);
            float p1 = __expf(sacc[j][1] - mn0);
            float p2 = __expf(sacc[j][2] - mn1);
            float p3 = __expf(sacc[j][3] - mn1);
            s0 += p0 + p1; s1 += p2 + p3;
            __half2 h01 = __floats2half2_rn(p0, p1);
            __half2 h23 = __floats2half2_rn(p2, p3);
            int ks = j >> 1, hi = (j & 1) * 2;
            aP[ks][hi]     = *(uint32_t*)&h01;
            aP[ks][hi + 1] = *(uint32_t*)&h23;
        }
        s0 += __shfl_xor_sync(0xffffffffu, s0, 1);
        s0 += __shfl_xor_sync(0xffffffffu, s0, 2);
        s1 += __shfl_xor_sync(0xffffffffu, s1, 1);
        s1 += __shfl_xor_sync(0xffffffffu, s1, 2);
        lrow0 = lrow0 * al0 + s0;
        lrow1 = lrow1 * al1 + s1;

#pragma unroll
        for (int j = 0; j < 16; ++j) {
            oacc[j][0] *= al0; oacc[j][1] *= al0;
            oacc[j][2] *= al1; oacc[j][3] *= al1;
        }

        // O += P @ V : 16 d-tiles, V frags via ldmatrix.trans
#pragma unroll
        for (int ks = 0; ks < 4; ++ks) {
#pragma unroll
            for (int p = 0; p < 8; ++p) {
                uint32_t vo = sV +
                    (uint32_t)((ks * 16 + l7 + k8 * 8) * FL_LDK) * 2 + (2 * p + hi16) * 16;
                uint32_t r0, r1, r2, r3;
                ldsm_x4_t(r0, r1, r2, r3, vo);
                uint32_t b0[2] = {r0, r1}, b1[2] = {r2, r3};
                mma_fp16(oacc[2 * p], aP[ks], b0);
                mma_fp16(oacc[2 * p + 1], aP[ks], b1);
            }
        }
    }

    // Epilogue: normalize, write fp16 to g_ATh
    float i0 = 1.f / lrow0, i1 = 1.f / lrow1;
    size_t row0 = qrow0 + wr + g;
#pragma unroll
    for (int j = 0; j < 16; ++j) {
        int col = h * HD + 8 * j + 2 * tg;
        *(__half2*)(g_ATh + row0 * HID + col) =
            __floats2half2_rn(oacc[j][0] * i0, oacc[j][1] * i0);
        *(__half2*)(g_ATh + (row0 + 8) * HID + col) =
            __floats2half2_rn(oacc[j][2] * i1, oacc[j][3] * i1);
    }
}

// ---------------------------------------------------------------------------
extern "C" void kernel_launch(void* const* d_in, const int* in_sizes, int n_in,
                              void* d_out, int out_size)
{
    (void)in_sizes; (void)n_in; (void)out_size;
    const float* X  = (const float*)d_in[0];
    const float* Wq = (const float*)d_in[1];
    const float* bq = (const float*)d_in[2];
    const float* Wk = (const float*)d_in[3];
    const float* bk = (const float*)d_in[4];
    const float* Wv = (const float*)d_in[5];
    const float* bv = (const float*)d_in[6];
    const float* Wo = (const float*)d_in[7];
    const float* bo = (const float*)d_in[8];
    float* out = (float*)d_out;

    (void)cudaFuncSetAttribute(flash_mma,
        cudaFuncAttributeMaxDynamicSharedMemorySize, FL_SMEM);
    (void)cudaFuncSetAttribute(qkv_mma,
        cudaFuncAttributeMaxDynamicSharedMemorySize, GSMEM64);
    (void)cudaFuncSetAttribute(oproj_mma,
        cudaFuncAttributeMaxDynamicSharedMemorySize, GSMEM);

    __half *xh, *wqh, *wkh, *wvh, *woh;
    cudaGetSymbolAddress((void**)&xh,  g_Xh);
    cudaGetSymbolAddress((void**)&wqh, g_WqTh);
    cudaGetSymbolAddress((void**)&wkh, g_WkTh);
    cudaGetSymbolAddress((void**)&wvh, g_WvTh);
    cudaGetSymbolAddress((void**)&woh, g_WoTh);

    // 1) merged converts to fp16
    convert_all<<<17408, 256>>>(X, Wq, Wk, Wv, Wo, xh, wqh, wkh, wvh, woh);

    // 2) QKV projection (64x128 tiles, 3 CTAs/SM)
    qkv_mma<<<1280, 128, GSMEM64>>>(bq, bk, bv);

    // 3) attention (256 threads, Br=128, 16 warps/SM)
    flash_mma<<<dim3(16, 32), 256, FL_SMEM>>>();

    // 4) O projection (256 threads, 8 warps, 16 warps/SM)
    oproj_mma<<<dim3(16, 32), 256, GSMEM>>>(bo, out);
}

// round 13
// speedup vs baseline: 1.0894x; 1.0894x over previous
#include <cuda_runtime.h>
#include <cuda_fp16.h>
#include <math.h>
#include <stdint.h>

// Problem constants
#define HID   2048
#define MTOT  4096          // B*S = 2*2048
#define KVD   256           // N_KV * HEAD_DIM
#define HD    128
#define SCALING 0.08838834764831845f  // 128^-0.5

// K-chunk-64 GEMM smem geometry (2-stage)
#define LDT64  72                        // 64 + 8 pad halves; 144B rows
#define OTILE  (128 * LDT64 * 2)         // 18432 B (128-row tile)
#define OSTAGE (2 * OTILE)               // 36864 B (A+B, oproj)
#define OSMEM  (2 * OSTAGE)              // 73728 B
#define QATILE (64 * LDT64 * 2)          // 9216 B
#define QBTILE (128 * LDT64 * 2)         // 18432 B
#define QSTAGE (QATILE + QBTILE)         // 27648 B
#define QSMEM  (2 * QSTAGE)              // 55296 B -> 3 CTAs/SM

// ---------------------------------------------------------------------------
// Scratch (device globals; no runtime allocation allowed)
// ---------------------------------------------------------------------------
__device__ __half g_Qh[(size_t)MTOT * HID];
__device__ __half g_Kh[(size_t)MTOT * KVD];
__device__ __half g_Vh[(size_t)MTOT * KVD];
__device__ __half g_ATh[(size_t)MTOT * HID];

__device__ __half g_Xh[(size_t)MTOT * HID];
__device__ __half g_WqTh[(size_t)HID * HID];
__device__ __half g_WkTh[(size_t)KVD * HID];
__device__ __half g_WvTh[(size_t)KVD * HID];
__device__ __half g_WoTh[(size_t)HID * HID];

// ---------------------------------------------------------------------------
// Helpers
// ---------------------------------------------------------------------------
__device__ __forceinline__ uint32_t smem_u32(const void* p) {
    uint32_t a;
    asm("{ .reg .u64 t; cvta.to.shared.u64 t, %1; cvt.u32.u64 %0, t; }"
        : "=r"(a) : "l"(p));
    return a;
}
__device__ __forceinline__ void cp16(uint32_t sa, const void* ga) {
    asm volatile("cp.async.cg.shared.global [%0], [%1], 16;"
                 :: "r"(sa), "l"(ga) : "memory");
}
#define CP_COMMIT() asm volatile("cp.async.commit_group;" ::: "memory")
#define CP_WAIT0()  asm volatile("cp.async.wait_group 0;" ::: "memory")

__device__ __forceinline__ void ldsm_x4(uint32_t& r0, uint32_t& r1,
                                        uint32_t& r2, uint32_t& r3, uint32_t a) {
    asm volatile("ldmatrix.sync.aligned.m8n8.x4.shared.b16 {%0,%1,%2,%3}, [%4];"
                 : "=r"(r0), "=r"(r1), "=r"(r2), "=r"(r3) : "r"(a));
}
__device__ __forceinline__ void ldsm_x4_t(uint32_t& r0, uint32_t& r1,
                                          uint32_t& r2, uint32_t& r3, uint32_t a) {
    asm volatile("ldmatrix.sync.aligned.m8n8.x4.trans.shared.b16 {%0,%1,%2,%3}, [%4];"
                 : "=r"(r0), "=r"(r1), "=r"(r2), "=r"(r3) : "r"(a));
}
__device__ __forceinline__ void mma_fp16(float* c, const uint32_t* a,
                                         const uint32_t* b) {
    asm volatile(
        "mma.sync.aligned.m16n8k16.row.col.f32.f16.f16.f32 "
        "{%0,%1,%2,%3}, {%4,%5,%6,%7}, {%8,%9}, {%0,%1,%2,%3};"
        : "+f"(c[0]), "+f"(c[1]), "+f"(c[2]), "+f"(c[3])
        : "r"(a[0]), "r"(a[1]), "r"(a[2]), "r"(a[3]), "r"(b[0]), "r"(b[1]));
}

// ---------------------------------------------------------------------------
// Merged converts: fp32 -> fp16 (X rows + 4 transposed weights), one kernel.
// ---------------------------------------------------------------------------
__device__ __forceinline__ void conv_T_tile(
    const float* __restrict__ W, __half* __restrict__ WT,
    int N, int K, int bx, int by, float* tile /* [32][33] */)
{
    int n0 = bx * 32, k0 = by * 32;
    int tx = threadIdx.x & 31, ty = threadIdx.x >> 5;
#pragma unroll
    for (int j = 0; j < 4; ++j)
        tile[(ty + 8 * j) * 33 + tx] = W[(size_t)(k0 + ty + 8 * j) * N + n0 + tx];
    __syncthreads();
#pragma unroll
    for (int j = 0; j < 4; ++j) {
        int nn = n0 + ty + 8 * j;
        WT[(size_t)nn * K + k0 + tx] = __float2half_rn(tile[tx * 33 + ty + 8 * j]);
    }
}

__global__ __launch_bounds__(256)
void convert_all(const float* __restrict__ X,
                 const float* __restrict__ Wq, const float* __restrict__ Wk,
                 const float* __restrict__ Wv, const float* __restrict__ Wo,
                 __half* __restrict__ xh, __half* __restrict__ wqh,
                 __half* __restrict__ wkh, __half* __restrict__ wvh,
                 __half* __restrict__ woh)
{
    __shared__ float tile[32 * 33];
    int id = blockIdx.x;
    if (id < 8192) {
        size_t i = ((size_t)id * 256 + threadIdx.x) * 4;
        float4 v = *(const float4*)(X + i);
        *(__half2*)(xh + i)     = __floats2half2_rn(v.x, v.y);
        *(__half2*)(xh + i + 2) = __floats2half2_rn(v.z, v.w);
        return;
    }
    id -= 8192;
    if (id < 4096)      { conv_T_tile(Wq, wqh, HID, HID, id & 63, id >> 6, tile); return; }
    id -= 4096;
    if (id < 512)       { conv_T_tile(Wk, wkh, KVD, HID, id & 7,  id >> 3, tile); return; }
    id -= 512;
    if (id < 512)       { conv_T_tile(Wv, wvh, KVD, HID, id & 7,  id >> 3, tile); return; }
    id -= 512;
    conv_T_tile(Wo, woh, HID, HID, id & 63, id >> 6, tile);
}

// ---------------------------------------------------------------------------
// QKV GEMM: 64x128 tiles, 128 threads, 4 warps (2m x 2n), warp tile 32x64.
// K-chunk 64, 2-stage cp.async (32 stages). 3 CTAs/SM. Outputs fp16.
// ---------------------------------------------------------------------------
__device__ void gemm64_body(
    const __half* __restrict__ A, const __half* __restrict__ B,
    const float* __restrict__ bias, __half* __restrict__ Ch,
    int ldc, int m0, int n0, float scale, char* smb)
{
    const int t    = threadIdx.x;
    const int lane = t & 31, wid = t >> 5;
    const int wm   = wid & 1, wn = wid >> 1;
    const int g    = lane >> 2, tg = lane & 3;
    const int l15  = lane & 15, l7 = lane & 7;
    const int hi16 = lane >> 4, k8 = (lane >> 3) & 1;
    const uint32_t sb = smem_u32(smb);

    float acc[2][8][4];
#pragma unroll
    for (int im = 0; im < 2; ++im)
#pragma unroll
        for (int in = 0; in < 8; ++in)
#pragma unroll
            for (int r = 0; r < 4; ++r) acc[im][in][r] = 0.f;

    auto prefetch = [&](int s) {
        const uint32_t base = sb + (uint32_t)(s & 1) * QSTAGE;
        const int k0 = s * 64;
        // A: 64 rows x 8 chunks = 512
#pragma unroll
        for (int i = 0; i < 4; ++i) {
            int idx = t + 128 * i;
            int r = idx >> 3, c = idx & 7;
            cp16(base + (uint32_t)(r * LDT64 + c * 8) * 2,
                 A + (size_t)(m0 + r) * HID + k0 + c * 8);
        }
        // B: 128 rows x 8 chunks = 1024
#pragma unroll
        for (int i = 0; i < 8; ++i) {
            int idx = t + 128 * i;
            int r = idx >> 3, c = idx & 7;
            cp16(base + QATILE + (uint32_t)(r * LDT64 + c * 8) * 2,
                 B + (size_t)(n0 + r) * HID + k0 + c * 8);
        }
        CP_COMMIT();
    };

    prefetch(0);

    for (int s = 0; s < 32; ++s) {
        CP_WAIT0();
        __syncthreads();
        if (s + 1 < 32) prefetch(s + 1);

        const uint32_t base = sb + (uint32_t)(s & 1) * QSTAGE;
#pragma unroll
        for (int kk = 0; kk < 64; kk += 16) {
            uint32_t ah[2][4], bh[8][2];
#pragma unroll
            for (int im = 0; im < 2; ++im) {
                uint32_t ao = base +
                    (uint32_t)((wm * 32 + im * 16 + l15) * LDT64 + kk) * 2 + hi16 * 16;
                ldsm_x4(ah[im][0], ah[im][1], ah[im][2], ah[im][3], ao);
            }
#pragma unroll
            for (int p = 0; p < 4; ++p) {
                uint32_t bo = base + QATILE +
                    (uint32_t)((wn * 64 + p * 16 + l7 + hi16 * 8) * LDT64 + kk) * 2 + k8 * 16;
                uint32_t r0, r1, r2, r3;
                ldsm_x4(r0, r1, r2, r3, bo);
                bh[2 * p][0] = r0;     bh[2 * p][1] = r1;
                bh[2 * p + 1][0] = r2; bh[2 * p + 1][1] = r3;
            }
#pragma unroll
            for (int im = 0; im < 2; ++im)
#pragma unroll
                for (int in = 0; in < 8; ++in)
                    mma_fp16(acc[im][in], ah[im], bh[in]);
        }
        __syncthreads();
    }

#pragma unroll
    for (int im = 0; im < 2; ++im) {
#pragma unroll
        for (int in = 0; in < 8; ++in) {
            int row = m0 + wm * 32 + im * 16 + g;
            int col = n0 + wn * 64 + in * 8 + 2 * tg;
            float2 b2 = *(const float2*)(bias + col);
            *(__half2*)(Ch + (size_t)row * ldc + col) =
                __floats2half2_rn((acc[im][in][0] + b2.x) * scale,
                                  (acc[im][in][1] + b2.y) * scale);
            *(__half2*)(Ch + (size_t)(row + 8) * ldc + col) =
                __floats2half2_rn((acc[im][in][2] + b2.x) * scale,
                                  (acc[im][in][3] + b2.y) * scale);
        }
    }
}

__global__ __launch_bounds__(128, 3)
void qkv_mma(const float* __restrict__ bq, const float* __restrict__ bk,
             const float* __restrict__ bv)
{
    extern __shared__ char smb[];
    int gx = blockIdx.x >> 6, my = blockIdx.x & 63;
    int m0 = my * 64;
    if (gx < 16) {
        gemm64_body(g_Xh, g_WqTh, bq, g_Qh, HID, m0, gx * 128, SCALING, smb);
    } else if (gx < 18) {
        gemm64_body(g_Xh, g_WkTh, bk, g_Kh, KVD, m0, (gx - 16) * 128, 1.f, smb);
    } else {
        gemm64_body(g_Xh, g_WvTh, bv, g_Vh, KVD, m0, (gx - 18) * 128, 1.f, smb);
    }
}

// ---------------------------------------------------------------------------
// O-proj GEMM (v2 warp layout, proven): 128 threads, 4 warps (2m x 2n),
// warp tile 64x64, CTA tile 128x128. K-chunk 64, 2-stage (32 stages).
// ---------------------------------------------------------------------------
__global__ __launch_bounds__(128, 2)
void oproj_mma(const float* __restrict__ bo, float* __restrict__ out)
{
    extern __shared__ char smb[];
    const int t    = threadIdx.x;
    const int lane = t & 31, wid = t >> 5;
    const int wm   = wid & 1, wn = wid >> 1;
    const int g    = lane >> 2, tg = lane & 3;
    const int l15  = lane & 15, l7 = lane & 7;
    const int hi16 = lane >> 4, k8 = (lane >> 3) & 1;
    const int m0 = blockIdx.y * 128, n0 = blockIdx.x * 128;
    const uint32_t sb = smem_u32(smb);
    const __half* A = g_ATh;
    const __half* B = g_WoTh;

    float acc[4][8][4];
#pragma unroll
    for (int im = 0; im < 4; ++im)
#pragma unroll
        for (int in = 0; in < 8; ++in)
#pragma unroll
            for (int r = 0; r < 4; ++r) acc[im][in][r] = 0.f;

    auto prefetch = [&](int s) {
        const uint32_t base = sb + (uint32_t)(s & 1) * OSTAGE;
        const int k0 = s * 64;
        // A and B: 128 rows x 8 chunks = 1024 each
#pragma unroll
        for (int i = 0; i < 8; ++i) {
            int idx = t + 128 * i;
            int r = idx >> 3, c = idx & 7;
            uint32_t so = base + (uint32_t)(r * LDT64 + c * 8) * 2;
            cp16(so,         A + (size_t)(m0 + r) * HID + k0 + c * 8);
            cp16(so + OTILE, B + (size_t)(n0 + r) * HID + k0 + c * 8);
        }
        CP_COMMIT();
    };

    prefetch(0);

    for (int s = 0; s < 32; ++s) {
        CP_WAIT0();
        __syncthreads();
        if (s + 1 < 32) prefetch(s + 1);

        const uint32_t base = sb + (uint32_t)(s & 1) * OSTAGE;
#pragma unroll
        for (int kk = 0; kk < 64; kk += 16) {
            uint32_t ah[4][4], bh[8][2];
#pragma unroll
            for (int im = 0; im < 4; ++im) {
                uint32_t ao = base +
                    (uint32_t)((wm * 64 + im * 16 + l15) * LDT64 + kk) * 2 + hi16 * 16;
                ldsm_x4(ah[im][0], ah[im][1], ah[im][2], ah[im][3], ao);
            }
#pragma unroll
            for (int p = 0; p < 4; ++p) {
                uint32_t bo2 = base + OTILE +
                    (uint32_t)((wn * 64 + p * 16 + l7 + hi16 * 8) * LDT64 + kk) * 2 + k8 * 16;
                uint32_t r0, r1, r2, r3;
                ldsm_x4(r0, r1, r2, r3, bo2);
                bh[2 * p][0] = r0;     bh[2 * p][1] = r1;
                bh[2 * p + 1][0] = r2; bh[2 * p + 1][1] = r3;
            }
#pragma unroll
            for (int im = 0; im < 4; ++im)
#pragma unroll
                for (int in = 0; in < 8; ++in)
                    mma_fp16(acc[im][in], ah[im], bh[in]);
        }
        __syncthreads();
    }

#pragma unroll
    for (int im = 0; im < 4; ++im) {
#pragma unroll
        for (int in = 0; in < 8; ++in) {
            int row = m0 + wm * 64 + im * 16 + g;
            int col = n0 + wn * 64 + in * 8 + 2 * tg;
            float2 b2 = *(const float2*)(bo + col);
            *(float2*)(out + (size_t)row * HID + col) =
                make_float2(acc[im][in][0] + b2.x, acc[im][in][1] + b2.y);
            *(float2*)(out + (size_t)(row + 8) * HID + col) =
                make_float2(acc[im][in][2] + b2.x, acc[im][in][3] + b2.y);
        }
    }
}

// ---------------------------------------------------------------------------
// Flash attention (R11 exact — proven).
// grid = (32 qblocks, 32 bh), 128 threads, Br=64, Bc=64, D=128.
// ---------------------------------------------------------------------------
#define FL_LDK  136
#define FL_TILE (64 * FL_LDK * 2)        // 17408 B
#define FL_SMEM (5 * FL_TILE)            // 87040 B

__global__ __launch_bounds__(128, 2)
void flash_mma()
{
    extern __shared__ __half fsm[];
    const uint32_t sQ  = smem_u32(fsm);
    const uint32_t sK0 = sQ + FL_TILE;
    const uint32_t sV0 = sQ + 3 * FL_TILE;

    const int t = threadIdx.x, lane = t & 31, warp = t >> 5;
    const int g = lane >> 2, tg = lane & 3;
    const int l15 = lane & 15, l7 = lane & 7;
    const int hi16 = lane >> 4, k8 = (lane >> 3) & 1;
    const int bh = blockIdx.y, b = bh >> 4, h = bh & 15, kvh = h >> 3;
    const int q0 = blockIdx.x * 64;
    const size_t qrow0 = (size_t)(b * 2048 + q0);
    const int wr = warp * 16;

    auto prefetch_kv = [&](int kb) {
        const uint32_t buf = (uint32_t)(kb & 1) * FL_TILE;
        const size_t krow0 = (size_t)(b * 2048 + kb * 64);
#pragma unroll
        for (int s = 0; s < 8; ++s) {
            int i = t + 128 * s;
            int r = i >> 4, c = i & 15;
            uint32_t so = (uint32_t)(r * FL_LDK + c * 8) * 2;
            size_t go = (krow0 + r) * KVD + kvh * HD + c * 8;
            cp16(sK0 + buf + so, g_Kh + go);
            cp16(sV0 + buf + so, g_Vh + go);
        }
        CP_COMMIT();
    };

    prefetch_kv(0);

#pragma unroll
    for (int s = 0; s < 8; ++s) {
        int i = t + 128 * s;
        int r = i >> 4, c = i & 15;
        *(uint4*)(fsm + r * FL_LDK + c * 8) =
            *(const uint4*)(g_Qh + (qrow0 + r) * HID + h * HD + c * 8);
    }
    __syncthreads();

    uint32_t aQ[8][4];
#pragma unroll
    for (int ks = 0; ks < 8; ++ks) {
        uint32_t ao = sQ + (uint32_t)((wr + l15) * FL_LDK + ks * 16) * 2 + hi16 * 16;
        ldsm_x4(aQ[ks][0], aQ[ks][1], aQ[ks][2], aQ[ks][3], ao);
    }

    float oacc[16][4];
#pragma unroll
    for (int j = 0; j < 16; ++j)
#pragma unroll
        for (int r = 0; r < 4; ++r) oacc[j][r] = 0.f;
    float mrow0 = -1e30f, mrow1 = -1e30f, lrow0 = 0.f, lrow1 = 0.f;

    for (int kb = 0; kb < 32; ++kb) {
        CP_WAIT0();
        __syncthreads();
        if (kb + 1 < 32) prefetch_kv(kb + 1);

        const uint32_t sK = sK0 + (uint32_t)(kb & 1) * FL_TILE;
        const uint32_t sV = sV0 + (uint32_t)(kb & 1) * FL_TILE;

        float sacc[8][4];
#pragma unroll
        for (int j = 0; j < 8; ++j)
#pragma unroll
            for (int r = 0; r < 4; ++r) sacc[j][r] = 0.f;
#pragma unroll
        for (int ks = 0; ks < 8; ++ks) {
#pragma unroll
            for (int p = 0; p < 4; ++p) {
                uint32_t bo = sK +
                    (uint32_t)((p * 16 + l7 + hi16 * 8) * FL_LDK + ks * 16) * 2 + k8 * 16;
                uint32_t r0, r1, r2, r3;
                ldsm_x4(r0, r1, r2, r3, bo);
                uint32_t b0[2] = {r0, r1}, b1[2] = {r2, r3};
                mma_fp16(sacc[2 * p], aQ[ks], b0);
                mma_fp16(sacc[2 * p + 1], aQ[ks], b1);
            }
        }

        float mx0 = -1e30f, mx1 = -1e30f;
#pragma unroll
        for (int j = 0; j < 8; ++j) {
            mx0 = fmaxf(mx0, fmaxf(sacc[j][0], sacc[j][1]));
            mx1 = fmaxf(mx1, fmaxf(sacc[j][2], sacc[j][3]));
        }
        mx0 = fmaxf(mx0, __shfl_xor_sync(0xffffffffu, mx0, 1));
        mx0 = fmaxf(mx0, __shfl_xor_sync(0xffffffffu, mx0, 2));
        mx1 = fmaxf(mx1, __shfl_xor_sync(0xffffffffu, mx1, 1));
        mx1 = fmaxf(mx1, __shfl_xor_sync(0xffffffffu, mx1, 2));
        float mn0 = fmaxf(mrow0, mx0), mn1 = fmaxf(mrow1, mx1);
        float al0 = __expf(mrow0 - mn0), al1 = __expf(mrow1 - mn1);
        mrow0 = mn0; mrow1 = mn1;

        uint32_t aP[4][4];
        float s0 = 0.f, s1 = 0.f;
#pragma unroll
        for (int j = 0; j < 8; ++j) {
            float p0 = __expf(sacc[j][0] - mn0);
            float p1 = __expf(sacc[j][1] - mn0);
            float p2 = __expf(sacc[j][2] - mn1);
            float p3 = __expf(sacc[j][3] - mn1);
            s0 += p0 + p1; s1 += p2 + p3;
            __half2 h01 = __floats2half2_rn(p0, p1);
            __half2 h23 = __floats2half2_rn(p2, p3);
            int ks = j >> 1, hi = (j & 1) * 2;
            aP[ks][hi]     = *(uint32_t*)&h01;
            aP[ks][hi + 1] = *(uint32_t*)&h23;
        }
        s0 += __shfl_xor_sync(0xffffffffu, s0, 1);
        s0 += __shfl_xor_sync(0xffffffffu, s0, 2);
        s1 += __shfl_xor_sync(0xffffffffu, s1, 1);
        s1 += __shfl_xor_sync(0xffffffffu, s1, 2);
        lrow0 = lrow0 * al0 + s0;
        lrow1 = lrow1 * al1 + s1;

#pragma unroll
        for (int j = 0; j < 16; ++j) {
            oacc[j][0] *= al0; oacc[j][1] *= al0;
            oacc[j][2] *= al1; oacc[j][3] *= al1;
        }

#pragma unroll
        for (int ks = 0; ks < 4; ++ks) {
#pragma unroll
            for (int p = 0; p < 8; ++p) {
                uint32_t vo = sV +
                    (uint32_t)((ks * 16 + l7 + k8 * 8) * FL_LDK) * 2 + (2 * p + hi16) * 16;
                uint32_t r0, r1, r2, r3;
                ldsm_x4_t(r0, r1, r2, r3, vo);
                uint32_t b0[2] = {r0, r1}, b1[2] = {r2, r3};
                mma_fp16(oacc[2 * p], aP[ks], b0);
                mma_fp16(oacc[2 * p + 1], aP[ks], b1);
            }
        }
    }

    float i0 = 1.f / lrow0, i1 = 1.f / lrow1;
    size_t row0 = qrow0 + wr + g;
#pragma unroll
    for (int j = 0; j < 16; ++j) {
        int col = h * HD + 8 * j + 2 * tg;
        *(__half2*)(g_ATh + row0 * HID + col) =
            __floats2half2_rn(oacc[j][0] * i0, oacc[j][1] * i0);
        *(__half2*)(g_ATh + (row0 + 8) * HID + col) =
            __floats2half2_rn(oacc[j][2] * i1, oacc[j][3] * i1);
    }
}

// ---------------------------------------------------------------------------
extern "C" void kernel_launch(void* const* d_in, const int* in_sizes, int n_in,
                              void* d_out, int out_size)
{
    (void)in_sizes; (void)n_in; (void)out_size;
    const float* X  = (const float*)d_in[0];
    const float* Wq = (const float*)d_in[1];
    const float* bq = (const float*)d_in[2];
    const float* Wk = (const float*)d_in[3];
    const float* bk = (const float*)d_in[4];
    const float* Wv = (const float*)d_in[5];
    const float* bv = (const float*)d_in[6];
    const float* Wo = (const float*)d_in[7];
    const float* bo = (const float*)d_in[8];
    float* out = (float*)d_out;

    (void)cudaFuncSetAttribute(flash_mma,
        cudaFuncAttributeMaxDynamicSharedMemorySize, FL_SMEM);
    (void)cudaFuncSetAttribute(qkv_mma,
        cudaFuncAttributeMaxDynamicSharedMemorySize, QSMEM);
    (void)cudaFuncSetAttribute(oproj_mma,
        cudaFuncAttributeMaxDynamicSharedMemorySize, OSMEM);

    __half *xh, *wqh, *wkh, *wvh, *woh;
    cudaGetSymbolAddress((void**)&xh,  g_Xh);
    cudaGetSymbolAddress((void**)&wqh, g_WqTh);
    cudaGetSymbolAddress((void**)&wkh, g_WkTh);
    cudaGetSymbolAddress((void**)&wvh, g_WvTh);
    cudaGetSymbolAddress((void**)&woh, g_WoTh);

    // 1) merged converts to fp16
    convert_all<<<17408, 256>>>(X, Wq, Wk, Wv, Wo, xh, wqh, wkh, wvh, woh);

    // 2) QKV projection (64x128 tiles, K-chunk 64, 3 CTAs/SM)
    qkv_mma<<<1280, 128, QSMEM>>>(bq, bk, bv);

    // 3) attention (R11 proven flash)
    flash_mma<<<dim3(32, 32), 128, FL_SMEM>>>();

    // 4) O projection (128x128 tiles, K-chunk 64)
    oproj_mma<<<dim3(16, 32), 128, OSMEM>>>(bo, out);
}

// round 14
// speedup vs baseline: 1.1237x; 1.0315x over previous
#include <cuda_runtime.h>
#include <cuda_fp16.h>
#include <math.h>
#include <stdint.h>

// Problem constants
#define HID   2048
#define MTOT  4096          // B*S = 2*2048
#define KVD   256           // N_KV * HEAD_DIM
#define HD    128
// 128^-0.5 * log2(e): Q feeds only attention; exp2-domain softmax
#define SCALING 0.1275174341514056f

// oproj smem geometry (K-chunk 32, 4-stage — R11 proven)
#define LDT    40
#define TILEB  (128 * LDT * 2)          // 10240 B
#define STAGE  (2 * TILEB)              // 20480 B
#define GSMEM  (4 * STAGE)              // 81920 B

// qkv smem geometry (K-chunk 64, 2-stage — R13 proven)
#define LDT64  72
#define QATILE (64 * LDT64 * 2)         // 9216 B
#define QBTILE (128 * LDT64 * 2)        // 18432 B
#define QSTAGE (QATILE + QBTILE)        // 27648 B
#define QSMEM  (2 * QSTAGE)             // 55296 B -> 3 CTAs/SM

// ---------------------------------------------------------------------------
// Scratch (device globals; no runtime allocation allowed)
// ---------------------------------------------------------------------------
__device__ __half g_Qh[(size_t)MTOT * HID];
__device__ __half g_Kh[(size_t)MTOT * KVD];
__device__ __half g_Vh[(size_t)MTOT * KVD];
__device__ __half g_ATh[(size_t)MTOT * HID];

__device__ __half g_Xh[(size_t)MTOT * HID];
__device__ __half g_WqTh[(size_t)HID * HID];
__device__ __half g_WkTh[(size_t)KVD * HID];
__device__ __half g_WvTh[(size_t)KVD * HID];
__device__ __half g_WoTh[(size_t)HID * HID];

// ---------------------------------------------------------------------------
// Helpers
// ---------------------------------------------------------------------------
__device__ __forceinline__ uint32_t smem_u32(const void* p) {
    uint32_t a;
    asm("{ .reg .u64 t; cvta.to.shared.u64 t, %1; cvt.u32.u64 %0, t; }"
        : "=r"(a) : "l"(p));
    return a;
}
__device__ __forceinline__ void cp16(uint32_t sa, const void* ga) {
    asm volatile("cp.async.cg.shared.global [%0], [%1], 16;"
                 :: "r"(sa), "l"(ga) : "memory");
}
#define CP_COMMIT() asm volatile("cp.async.commit_group;" ::: "memory")
#define CP_WAIT0()  asm volatile("cp.async.wait_group 0;" ::: "memory")

__device__ __forceinline__ void ldsm_x4(uint32_t& r0, uint32_t& r1,
                                        uint32_t& r2, uint32_t& r3, uint32_t a) {
    asm volatile("ldmatrix.sync.aligned.m8n8.x4.shared.b16 {%0,%1,%2,%3}, [%4];"
                 : "=r"(r0), "=r"(r1), "=r"(r2), "=r"(r3) : "r"(a));
}
__device__ __forceinline__ void ldsm_x4_t(uint32_t& r0, uint32_t& r1,
                                          uint32_t& r2, uint32_t& r3, uint32_t a) {
    asm volatile("ldmatrix.sync.aligned.m8n8.x4.trans.shared.b16 {%0,%1,%2,%3}, [%4];"
                 : "=r"(r0), "=r"(r1), "=r"(r2), "=r"(r3) : "r"(a));
}
__device__ __forceinline__ void mma_fp16(float* c, const uint32_t* a,
                                         const uint32_t* b) {
    asm volatile(
        "mma.sync.aligned.m16n8k16.row.col.f32.f16.f16.f32 "
        "{%0,%1,%2,%3}, {%4,%5,%6,%7}, {%8,%9}, {%0,%1,%2,%3};"
        : "+f"(c[0]), "+f"(c[1]), "+f"(c[2]), "+f"(c[3])
        : "r"(a[0]), "r"(a[1]), "r"(a[2]), "r"(a[3]), "r"(b[0]), "r"(b[1]));
}

// ---------------------------------------------------------------------------
// Merged converts: fp32 -> fp16 (X rows + 4 transposed weights), one kernel.
// ---------------------------------------------------------------------------
__device__ __forceinline__ void conv_T_tile(
    const float* __restrict__ W, __half* __restrict__ WT,
    int N, int K, int bx, int by, float* tile /* [32][33] */)
{
    int n0 = bx * 32, k0 = by * 32;
    int tx = threadIdx.x & 31, ty = threadIdx.x >> 5;
#pragma unroll
    for (int j = 0; j < 4; ++j)
        tile[(ty + 8 * j) * 33 + tx] = W[(size_t)(k0 + ty + 8 * j) * N + n0 + tx];
    __syncthreads();
#pragma unroll
    for (int j = 0; j < 4; ++j) {
        int nn = n0 + ty + 8 * j;
        WT[(size_t)nn * K + k0 + tx] = __float2half_rn(tile[tx * 33 + ty + 8 * j]);
    }
}

__global__ __launch_bounds__(256)
void convert_all(const float* __restrict__ X,
                 const float* __restrict__ Wq, const float* __restrict__ Wk,
                 const float* __restrict__ Wv, const float* __restrict__ Wo,
                 __half* __restrict__ xh, __half* __restrict__ wqh,
                 __half* __restrict__ wkh, __half* __restrict__ wvh,
                 __half* __restrict__ woh)
{
    __shared__ float tile[32 * 33];
    int id = blockIdx.x;
    if (id < 8192) {
        size_t i = ((size_t)id * 256 + threadIdx.x) * 4;
        float4 v = *(const float4*)(X + i);
        *(__half2*)(xh + i)     = __floats2half2_rn(v.x, v.y);
        *(__half2*)(xh + i + 2) = __floats2half2_rn(v.z, v.w);
        return;
    }
    id -= 8192;
    if (id < 4096)      { conv_T_tile(Wq, wqh, HID, HID, id & 63, id >> 6, tile); return; }
    id -= 4096;
    if (id < 512)       { conv_T_tile(Wk, wkh, KVD, HID, id & 7,  id >> 3, tile); return; }
    id -= 512;
    if (id < 512)       { conv_T_tile(Wv, wvh, KVD, HID, id & 7,  id >> 3, tile); return; }
    id -= 512;
    conv_T_tile(Wo, woh, HID, HID, id & 63, id >> 6, tile);
}

// ---------------------------------------------------------------------------
// QKV GEMM (R13 proven): 64x128 tiles, 128 threads, warp tile 32x64,
// K-chunk 64, 2-stage cp.async, 3 CTAs/SM. Outputs fp16.
// ---------------------------------------------------------------------------
__device__ void gemm64_body(
    const __half* __restrict__ A, const __half* __restrict__ B,
    const float* __restrict__ bias, __half* __restrict__ Ch,
    int ldc, int m0, int n0, float scale, char* smb)
{
    const int t    = threadIdx.x;
    const int lane = t & 31, wid = t >> 5;
    const int wm   = wid & 1, wn = wid >> 1;
    const int g    = lane >> 2, tg = lane & 3;
    const int l15  = lane & 15, l7 = lane & 7;
    const int hi16 = lane >> 4, k8 = (lane >> 3) & 1;
    const uint32_t sb = smem_u32(smb);

    float acc[2][8][4];
#pragma unroll
    for (int im = 0; im < 2; ++im)
#pragma unroll
        for (int in = 0; in < 8; ++in)
#pragma unroll
            for (int r = 0; r < 4; ++r) acc[im][in][r] = 0.f;

    auto prefetch = [&](int s) {
        const uint32_t base = sb + (uint32_t)(s & 1) * QSTAGE;
        const int k0 = s * 64;
#pragma unroll
        for (int i = 0; i < 4; ++i) {
            int idx = t + 128 * i;
            int r = idx >> 3, c = idx & 7;
            cp16(base + (uint32_t)(r * LDT64 + c * 8) * 2,
                 A + (size_t)(m0 + r) * HID + k0 + c * 8);
        }
#pragma unroll
        for (int i = 0; i < 8; ++i) {
            int idx = t + 128 * i;
            int r = idx >> 3, c = idx & 7;
            cp16(base + QATILE + (uint32_t)(r * LDT64 + c * 8) * 2,
                 B + (size_t)(n0 + r) * HID + k0 + c * 8);
        }
        CP_COMMIT();
    };

    prefetch(0);

    for (int s = 0; s < 32; ++s) {
        CP_WAIT0();
        __syncthreads();
        if (s + 1 < 32) prefetch(s + 1);

        const uint32_t base = sb + (uint32_t)(s & 1) * QSTAGE;
#pragma unroll
        for (int kk = 0; kk < 64; kk += 16) {
            uint32_t ah[2][4], bh[8][2];
#pragma unroll
            for (int im = 0; im < 2; ++im) {
                uint32_t ao = base +
                    (uint32_t)((wm * 32 + im * 16 + l15) * LDT64 + kk) * 2 + hi16 * 16;
                ldsm_x4(ah[im][0], ah[im][1], ah[im][2], ah[im][3], ao);
            }
#pragma unroll
            for (int p = 0; p < 4; ++p) {
                uint32_t bo = base + QATILE +
                    (uint32_t)((wn * 64 + p * 16 + l7 + hi16 * 8) * LDT64 + kk) * 2 + k8 * 16;
                uint32_t r0, r1, r2, r3;
                ldsm_x4(r0, r1, r2, r3, bo);
                bh[2 * p][0] = r0;     bh[2 * p][1] = r1;
                bh[2 * p + 1][0] = r2; bh[2 * p + 1][1] = r3;
            }
#pragma unroll
            for (int im = 0; im < 2; ++im)
#pragma unroll
                for (int in = 0; in < 8; ++in)
                    mma_fp16(acc[im][in], ah[im], bh[in]);
        }
        __syncthreads();
    }

#pragma unroll
    for (int im = 0; im < 2; ++im) {
#pragma unroll
        for (int in = 0; in < 8; ++in) {
            int row = m0 + wm * 32 + im * 16 + g;
            int col = n0 + wn * 64 + in * 8 + 2 * tg;
            float2 b2 = *(const float2*)(bias + col);
            *(__half2*)(Ch + (size_t)row * ldc + col) =
                __floats2half2_rn((acc[im][in][0] + b2.x) * scale,
                                  (acc[im][in][1] + b2.y) * scale);
            *(__half2*)(Ch + (size_t)(row + 8) * ldc + col) =
                __floats2half2_rn((acc[im][in][2] + b2.x) * scale,
                                  (acc[im][in][3] + b2.y) * scale);
        }
    }
}

__global__ __launch_bounds__(128, 3)
void qkv_mma(const float* __restrict__ bq, const float* __restrict__ bk,
             const float* __restrict__ bv)
{
    extern __shared__ char smb[];
    int gx = blockIdx.x >> 6, my = blockIdx.x & 63;
    int m0 = my * 64;
    if (gx < 16) {
        gemm64_body(g_Xh, g_WqTh, bq, g_Qh, HID, m0, gx * 128, SCALING, smb);
    } else if (gx < 18) {
        gemm64_body(g_Xh, g_WkTh, bk, g_Kh, KVD, m0, (gx - 16) * 128, 1.f, smb);
    } else {
        gemm64_body(g_Xh, g_WvTh, bv, g_Vh, KVD, m0, (gx - 18) * 128, 1.f, smb);
    }
}

// ---------------------------------------------------------------------------
// O-proj GEMM (R11 proven): 128 threads, 4 warps (2m x 2n), warp tile 64x64,
// CTA tile 128x128, K-chunk 32, 4-stage cp.async.
// ---------------------------------------------------------------------------
__global__ __launch_bounds__(128, 2)
void oproj_mma(const float* __restrict__ bo, float* __restrict__ out)
{
    extern __shared__ char smb[];
    const int t    = threadIdx.x;
    const int lane = t & 31, wid = t >> 5;
    const int wm   = wid & 1, wn = wid >> 1;
    const int g    = lane >> 2, tg = lane & 3;
    const int l15  = lane & 15, l7 = lane & 7;
    const int hi16 = lane >> 4, k8 = (lane >> 3) & 1;
    const int m0 = blockIdx.y * 128, n0 = blockIdx.x * 128;
    const uint32_t sb = smem_u32(smb);
    const __half* A = g_ATh;
    const __half* B = g_WoTh;

    float acc[4][8][4];
#pragma unroll
    for (int im = 0; im < 4; ++im)
#pragma unroll
        for (int in = 0; in < 8; ++in)
#pragma unroll
            for (int r = 0; r < 4; ++r) acc[im][in][r] = 0.f;

    auto prefetch = [&](int s) {
        const uint32_t base = sb + (uint32_t)(s & 3) * STAGE;
        const int k0 = s * 32;
#pragma unroll
        for (int i = 0; i < 4; ++i) {
            int idx = t + 128 * i;
            int r = idx >> 2, c = idx & 3;
            uint32_t so = base + (uint32_t)(r * LDT + c * 8) * 2;
            cp16(so,         A + (size_t)(m0 + r) * HID + k0 + c * 8);
            cp16(so + TILEB, B + (size_t)(n0 + r) * HID + k0 + c * 8);
        }
        CP_COMMIT();
    };

    prefetch(0); prefetch(1); prefetch(2);

    for (int s = 0; s < 64; ++s) {
        if (s < 62)       asm volatile("cp.async.wait_group 2;" ::: "memory");
        else if (s == 62) asm volatile("cp.async.wait_group 1;" ::: "memory");
        else              asm volatile("cp.async.wait_group 0;" ::: "memory");
        __syncthreads();
        if (s + 3 < 64) prefetch(s + 3);

        const uint32_t base = sb + (uint32_t)(s & 3) * STAGE;
#pragma unroll
        for (int kk = 0; kk < 32; kk += 16) {
            uint32_t ah[4][4], bh[8][2];
#pragma unroll
            for (int im = 0; im < 4; ++im) {
                uint32_t ao = base +
                    (uint32_t)((wm * 64 + im * 16 + l15) * LDT + kk) * 2 + hi16 * 16;
                ldsm_x4(ah[im][0], ah[im][1], ah[im][2], ah[im][3], ao);
            }
#pragma unroll
            for (int p = 0; p < 4; ++p) {
                uint32_t bo2 = base + TILEB +
                    (uint32_t)((wn * 64 + p * 16 + l7 + hi16 * 8) * LDT + kk) * 2 + k8 * 16;
                uint32_t r0, r1, r2, r3;
                ldsm_x4(r0, r1, r2, r3, bo2);
                bh[2 * p][0] = r0;     bh[2 * p][1] = r1;
                bh[2 * p + 1][0] = r2; bh[2 * p + 1][1] = r3;
            }
#pragma unroll
            for (int im = 0; im < 4; ++im)
#pragma unroll
                for (int in = 0; in < 8; ++in)
                    mma_fp16(acc[im][in], ah[im], bh[in]);
        }
    }

#pragma unroll
    for (int im = 0; im < 4; ++im) {
#pragma unroll
        for (int in = 0; in < 8; ++in) {
            int row = m0 + wm * 64 + im * 16 + g;
            int col = n0 + wn * 64 + in * 8 + 2 * tg;
            float2 b2 = *(const float2*)(bo + col);
            *(float2*)(out + (size_t)row * HID + col) =
                make_float2(acc[im][in][0] + b2.x, acc[im][in][1] + b2.y);
            *(float2*)(out + (size_t)(row + 8) * HID + col) =
                make_float2(acc[im][in][2] + b2.x, acc[im][in][3] + b2.y);
        }
    }
}

// ---------------------------------------------------------------------------
// Flash attention (R11 structure; softmax in exp2 domain — log2e folded
// into Q scale). grid = (32 qblocks, 32 bh), 128 threads, Br=64, Bc=64.
// ---------------------------------------------------------------------------
#define FL_LDK  136
#define FL_TILE (64 * FL_LDK * 2)        // 17408 B
#define FL_SMEM (5 * FL_TILE)            // 87040 B

__global__ __launch_bounds__(128, 2)
void flash_mma()
{
    extern __shared__ __half fsm[];
    const uint32_t sQ  = smem_u32(fsm);
    const uint32_t sK0 = sQ + FL_TILE;
    const uint32_t sV0 = sQ + 3 * FL_TILE;

    const int t = threadIdx.x, lane = t & 31, warp = t >> 5;
    const int g = lane >> 2, tg = lane & 3;
    const int l15 = lane & 15, l7 = lane & 7;
    const int hi16 = lane >> 4, k8 = (lane >> 3) & 1;
    const int bh = blockIdx.y, b = bh >> 4, h = bh & 15, kvh = h >> 3;
    const int q0 = blockIdx.x * 64;
    const size_t qrow0 = (size_t)(b * 2048 + q0);
    const int wr = warp * 16;

    auto prefetch_kv = [&](int kb) {
        const uint32_t buf = (uint32_t)(kb & 1) * FL_TILE;
        const size_t krow0 = (size_t)(b * 2048 + kb * 64);
#pragma unroll
        for (int s = 0; s < 8; ++s) {
            int i = t + 128 * s;
            int r = i >> 4, c = i & 15;
            uint32_t so = (uint32_t)(r * FL_LDK + c * 8) * 2;
            size_t go = (krow0 + r) * KVD + kvh * HD + c * 8;
            cp16(sK0 + buf + so, g_Kh + go);
            cp16(sV0 + buf + so, g_Vh + go);
        }
        CP_COMMIT();
    };

    prefetch_kv(0);

#pragma unroll
    for (int s = 0; s < 8; ++s) {
        int i = t + 128 * s;
        int r = i >> 4, c = i & 15;
        *(uint4*)(fsm + r * FL_LDK + c * 8) =
            *(const uint4*)(g_Qh + (qrow0 + r) * HID + h * HD + c * 8);
    }
    __syncthreads();

    uint32_t aQ[8][4];
#pragma unroll
    for (int ks = 0; ks < 8; ++ks) {
        uint32_t ao = sQ + (uint32_t)((wr + l15) * FL_LDK + ks * 16) * 2 + hi16 * 16;
        ldsm_x4(aQ[ks][0], aQ[ks][1], aQ[ks][2], aQ[ks][3], ao);
    }

    float oacc[16][4];
#pragma unroll
    for (int j = 0; j < 16; ++j)
#pragma unroll
        for (int r = 0; r < 4; ++r) oacc[j][r] = 0.f;
    float mrow0 = -1e30f, mrow1 = -1e30f, lrow0 = 0.f, lrow1 = 0.f;

    for (int kb = 0; kb < 32; ++kb) {
        CP_WAIT0();
        __syncthreads();
        if (kb + 1 < 32) prefetch_kv(kb + 1);

        const uint32_t sK = sK0 + (uint32_t)(kb & 1) * FL_TILE;
        const uint32_t sV = sV0 + (uint32_t)(kb & 1) * FL_TILE;

        float sacc[8][4];
#pragma unroll
        for (int j = 0; j < 8; ++j)
#pragma unroll
            for (int r = 0; r < 4; ++r) sacc[j][r] = 0.f;
#pragma unroll
        for (int ks = 0; ks < 8; ++ks) {
#pragma unroll
            for (int p = 0; p < 4; ++p) {
                uint32_t bo = sK +
                    (uint32_t)((p * 16 + l7 + hi16 * 8) * FL_LDK + ks * 16) * 2 + k8 * 16;
                uint32_t r0, r1, r2, r3;
                ldsm_x4(r0, r1, r2, r3, bo);
                uint32_t b0[2] = {r0, r1}, b1[2] = {r2, r3};
                mma_fp16(sacc[2 * p], aQ[ks], b0);
                mma_fp16(sacc[2 * p + 1], aQ[ks], b1);
            }
        }

        // Online softmax in exp2 domain (S already scaled by log2e via Q)
        float mx0 = -1e30f, mx1 = -1e30f;
#pragma unroll
        for (int j = 0; j < 8; ++j) {
            mx0 = fmaxf(mx0, fmaxf(sacc[j][0], sacc[j][1]));
            mx1 = fmaxf(mx1, fmaxf(sacc[j][2], sacc[j][3]));
        }
        mx0 = fmaxf(mx0, __shfl_xor_sync(0xffffffffu, mx0, 1));
        mx0 = fmaxf(mx0, __shfl_xor_sync(0xffffffffu, mx0, 2));
        mx1 = fmaxf(mx1, __shfl_xor_sync(0xffffffffu, mx1, 1));
        mx1 = fmaxf(mx1, __shfl_xor_sync(0xffffffffu, mx1, 2));
        float mn0 = fmaxf(mrow0, mx0), mn1 = fmaxf(mrow1, mx1);
        float al0 = exp2f(mrow0 - mn0), al1 = exp2f(mrow1 - mn1);
        mrow0 = mn0; mrow1 = mn1;

        uint32_t aP[4][4];
        float s0 = 0.f, s1 = 0.f;
#pragma unroll
        for (int j = 0; j < 8; ++j) {
            float p0 = exp2f(sacc[j][0] - mn0);
            float p1 = exp2f(sacc[j][1] - mn0);
            float p2 = exp2f(sacc[j][2] - mn1);
            float p3 = exp2f(sacc[j][3] - mn1);
            s0 += p0 + p1; s1 += p2 + p3;
            __half2 h01 = __floats2half2_rn(p0, p1);
            __half2 h23 = __floats2half2_rn(p2, p3);
            int ks = j >> 1, hi = (j & 1) * 2;
            aP[ks][hi]     = *(uint32_t*)&h01;
            aP[ks][hi + 1] = *(uint32_t*)&h23;
        }
        s0 += __shfl_xor_sync(0xffffffffu, s0, 1);
        s0 += __shfl_xor_sync(0xffffffffu, s0, 2);
        s1 += __shfl_xor_sync(0xffffffffu, s1, 1);
        s1 += __shfl_xor_sync(0xffffffffu, s1, 2);
        lrow0 = lrow0 * al0 + s0;
        lrow1 = lrow1 * al1 + s1;

#pragma unroll
        for (int j = 0; j < 16; ++j) {
            oacc[j][0] *= al0; oacc[j][1] *= al0;
            oacc[j][2] *= al1; oacc[j][3] *= al1;
        }

#pragma unroll
        for (int ks = 0; ks < 4; ++ks) {
#pragma unroll
            for (int p = 0; p < 8; ++p) {
                uint32_t vo = sV +
                    (uint32_t)((ks * 16 + l7 + k8 * 8) * FL_LDK) * 2 + (2 * p + hi16) * 16;
                uint32_t r0, r1, r2, r3;
                ldsm_x4_t(r0, r1, r2, r3, vo);
                uint32_t b0[2] = {r0, r1}, b1[2] = {r2, r3};
                mma_fp16(oacc[2 * p], aP[ks], b0);
                mma_fp16(oacc[2 * p + 1], aP[ks], b1);
            }
        }
    }

    float i0 = 1.f / lrow0, i1 = 1.f / lrow1;
    size_t row0 = qrow0 + wr + g;
#pragma unroll
    for (int j = 0; j < 16; ++j) {
        int col = h * HD + 8 * j + 2 * tg;
        *(__half2*)(g_ATh + row0 * HID + col) =
            __floats2half2_rn(oacc[j][0] * i0, oacc[j][1] * i0);
        *(__half2*)(g_ATh + (row0 + 8) * HID + col) =
            __floats2half2_rn(oacc[j][2] * i1, oacc[j][3] * i1);
    }
}

// ---------------------------------------------------------------------------
extern "C" void kernel_launch(void* const* d_in, const int* in_sizes, int n_in,
                              void* d_out, int out_size)
{
    (void)in_sizes; (void)n_in; (void)out_size;
    const float* X  = (const float*)d_in[0];
    const float* Wq = (const float*)d_in[1];
    const float* bq = (const float*)d_in[2];
    const float* Wk = (const float*)d_in[3];
    const float* bk = (const float*)d_in[4];
    const float* Wv = (const float*)d_in[5];
    const float* bv = (const float*)d_in[6];
    const float* Wo = (const float*)d_in[7];
    const float* bo = (const float*)d_in[8];
    float* out = (float*)d_out;

    (void)cudaFuncSetAttribute(flash_mma,
        cudaFuncAttributeMaxDynamicSharedMemorySize, FL_SMEM);
    (void)cudaFuncSetAttribute(qkv_mma,
        cudaFuncAttributeMaxDynamicSharedMemorySize, QSMEM);
    (void)cudaFuncSetAttribute(oproj_mma,
        cudaFuncAttributeMaxDynamicSharedMemorySize, GSMEM);

    __half *xh, *wqh, *wkh, *wvh, *woh;
    cudaGetSymbolAddress((void**)&xh,  g_Xh);
    cudaGetSymbolAddress((void**)&wqh, g_WqTh);
    cudaGetSymbolAddress((void**)&wkh, g_WkTh);
    cudaGetSymbolAddress((void**)&wvh, g_WvTh);
    cudaGetSymbolAddress((void**)&woh, g_WoTh);

    // 1) merged converts to fp16
    convert_all<<<17408, 256>>>(X, Wq, Wk, Wv, Wo, xh, wqh, wkh, wvh, woh);

    // 2) QKV projection (64x128 tiles, K-chunk 64, 3 CTAs/SM)
    qkv_mma<<<1280, 128, QSMEM>>>(bq, bk, bv);

    // 3) attention (exp2-domain softmax)
    flash_mma<<<dim3(32, 32), 128, FL_SMEM>>>();

    // 4) O projection (R11 proven 4-stage K32)
    oproj_mma<<<dim3(16, 32), 128, GSMEM>>>(bo, out);
}